// round 14
// baseline (speedup 1.0000x reference)
#include <cuda_runtime.h>
#include <math.h>
#include <stdint.h>

#define Bn 64
#define Dn 256
#define Hn 512
#define Rn 32
#define CLIPV 50.0f

// Output layout (concatenation of the returned tuple, fp32):
//   v_new      [64,512]      @ 0
//   new_h      [64,512]      @ 32768
//   dU_new     [64,512,512]  @ 65536
//   new_trace_e[64,512]      @ 16842752
//   new_trace_E[64,512,512]  @ 16875520
#define OFF_V    ((size_t)0)
#define OFF_NH   ((size_t)32768)
#define OFF_DU   ((size_t)65536)
#define OFF_TEO  ((size_t)16842752)
#define OFF_TEE  ((size_t)16875520)

// Device-global scratch (allocation-free).
// g_rowflag: producer/consumer flags. Zero-initialized at load; each launch
// leaves them zero again (sole consumer resets) -> graph-replay safe.
__device__ float g_up[Hn * Hn];
__device__ float g_lo[Hn * Hn];
__device__ float g_suMod[Bn];
__device__ float g_sE;
__device__ float g_omU;
__device__ int   g_rowflag[Bn * Hn];

__device__ __forceinline__ float sigmoidf_(float x) {
    return 1.0f / (1.0f + expf(-x));
}
__device__ __forceinline__ int ld_acquire_gpu(const int* p) {
    int v;
    asm volatile("ld.global.acquire.gpu.b32 %0, [%1];"
                 : "=r"(v) : "l"(p) : "memory");
    return v;
}
__device__ __forceinline__ void st_release_gpu(int* p, int v) {
    asm volatile("st.global.release.gpu.b32 [%0], %1;"
                 :: "l"(p), "r"(v) : "memory");
}

// ---------------------------------------------------------------------------
// Prep kernel: 320 blocks x 256 threads (~4us, serial).
//   [0,64)   mod blocks: g_suMod[b] (+ scalars at b==0).
//   [64,320) uplo blocks: clip bounds, 2 i-rows per block.
// ---------------------------------------------------------------------------
__global__ __launch_bounds__(256) void prep_kernel(
    const float* __restrict__ x, const float* __restrict__ h,
    const float* __restrict__ x2h_w, const float* __restrict__ x2h_b,
    const float* __restrict__ h2h_w, const float* __restrict__ h2h_b,
    const float* __restrict__ alpha, const float* __restrict__ tau_U,
    const float* __restrict__ tau_E) {
    const int bx   = blockIdx.x;
    const int tid  = threadIdx.x;
    const int warp = tid >> 5;
    const int lane = tid & 31;

    if (bx < 64) {
        const int b = bx;
        __shared__ float sm[8];
        const float4* xb = (const float4*)(x + (size_t)b * Dn);
        const float4* hb = (const float4*)(h + (size_t)b * Hn);

        float acc = 0.f;
#pragma unroll
        for (int t = 0; t < 4; t++) {
            const int o = Hn + warp + 8 * t;
            const float4* xw = (const float4*)(x2h_w + (size_t)o * Dn);
            const float4* hw = (const float4*)(h2h_w + (size_t)o * Hn);
            float s = 0.f;
#pragma unroll
            for (int c = 0; c < 2; c++) {
                const float4 W4 = xw[c * 32 + lane];
                const float4 V4 = xb[c * 32 + lane];
                s = fmaf(W4.x, V4.x, s); s = fmaf(W4.y, V4.y, s);
                s = fmaf(W4.z, V4.z, s); s = fmaf(W4.w, V4.w, s);
            }
#pragma unroll
            for (int c = 0; c < 4; c++) {
                const float4 W4 = hw[c * 32 + lane];
                const float4 V4 = hb[c * 32 + lane];
                s = fmaf(W4.x, V4.x, s); s = fmaf(W4.y, V4.y, s);
                s = fmaf(W4.z, V4.z, s); s = fmaf(W4.w, V4.w, s);
            }
#pragma unroll
            for (int off = 16; off; off >>= 1)
                s += __shfl_xor_sync(0xffffffffu, s, off);
            if (lane == 0) acc += fmaxf(s + x2h_b[o] + h2h_b[o], 0.f);
        }
        if (lane == 0) sm[warp] = acc;
        __syncthreads();
        if (tid == 0) {
            float m = 0.f;
#pragma unroll
            for (int w = 0; w < 8; w++) m += sm[w];
            const float sU = sigmoidf_(tau_U[0]);
            g_suMod[b] = sU * m;
            if (b == 0) {
                g_sE  = sigmoidf_(tau_E[0]);
                g_omU = 1.0f - sU;
            }
        }
        return;
    }

    // uplo blocks: 2 i-rows per block
    const int i  = (bx - 64) * 2 + (tid >> 7);
    const int j0 = (tid & 127) * 4;
    const float4 W = __ldg((const float4*)(h2h_w + (size_t)i * Hn + j0));
    const float4 A = __ldg((const float4*)(alpha + (size_t)i * Hn + j0));
    float4 up, lo;
    { const float d = fmaxf(A.x, 0.f) + 1e-8f;
      up.x = fmaxf(CLIPV - W.x, 0.f) / d;  lo.x = -fmaxf(CLIPV + W.x, 0.f) / d; }
    { const float d = fmaxf(A.y, 0.f) + 1e-8f;
      up.y = fmaxf(CLIPV - W.y, 0.f) / d;  lo.y = -fmaxf(CLIPV + W.y, 0.f) / d; }
    { const float d = fmaxf(A.z, 0.f) + 1e-8f;
      up.z = fmaxf(CLIPV - W.z, 0.f) / d;  lo.z = -fmaxf(CLIPV + W.z, 0.f) / d; }
    { const float d = fmaxf(A.w, 0.f) + 1e-8f;
      up.w = fmaxf(CLIPV - W.w, 0.f) / d;  lo.w = -fmaxf(CLIPV + W.w, 0.f) / d; }
    *(float4*)(g_up + (size_t)i * Hn + j0) = up;
    *(float4*)(g_lo + (size_t)i * Hn + j0) = lo;
}

// ---------------------------------------------------------------------------
// Mega kernel: producer/consumer overlap in ONE launch. 2304 blocks x 256 thr.
//  [0,256)    p1 producer blocks (lead the grid -> scheduled first, never
//             wait). Warp W = bx*8+warp owns i = W&511, b-group = W>>9;
//             loops 16 b: dv reduction over the dU row (dU read DEFAULT ->
//             L2-resident for the consumer), then lane0 writes
//             v/new_h/new_trace_e and RELEASE-stores g_rowflag[row]=1.
//  [256,2304) p2 consumer blocks. Block owns 16 consecutive rows (same b).
//             Per 2-row step: prefetch next step's du/tE streams FIRST, then
//             acquire-spin on this step's row flag (__nanosleep backoff),
//             then epilogue (dU_new / trace_E_new via __stcs).
//             Sole consumer of its flags -> resets them at the end.
// No atomics; fully deterministic; deadlock-free (producers precede in
// schedule order and never block).
// ---------------------------------------------------------------------------
__global__ __launch_bounds__(256, 4) void mega_kernel(
    const float* __restrict__ x, const float* __restrict__ h,
    const float* __restrict__ v, const float* __restrict__ dU,
    const float* __restrict__ trace_e, const float* __restrict__ trace_E,
    const float* __restrict__ x2h_w, const float* __restrict__ x2h_b,
    const float* __restrict__ h2h_w, const float* __restrict__ h2h_b,
    const float* __restrict__ alpha, const float* __restrict__ tau_v,
    const float* __restrict__ tau_e, float* __restrict__ out) {
    const int bx   = blockIdx.x;
    const int tid  = threadIdx.x;
    const int warp = tid >> 5;
    const int lane = tid & 31;

    const float4* dU4 = (const float4*)dU;

    if (bx < 256) {
        // ================= p1 producer =================
        const int W  = bx * 8 + warp;      // 0..2047
        const int i  = W & 511;
        const int b0 = (W >> 9) * 16;

        const float bias = x2h_b[i] + h2h_b[i];
        const float sv   = sigmoidf_(tau_v[i]);
        const float se   = sigmoidf_(tau_e[i]);

        const float4* a4p  = (const float4*)alpha + ((size_t)i << 7);
        const float4* w4p  = (const float4*)h2h_w + ((size_t)i << 7);
        const float4* xw4p = (const float4*)x2h_w + ((size_t)i << 6);

        for (int bb = 0; bb < 16; bb++) {
            const int b = b0 + bb;
            const size_t row  = (size_t)b * Hn + i;
            const size_t row4 = row << 7;

            float p0 = 0.f, p1 = 0.f, p2 = 0.f, p3 = 0.f;
#pragma unroll
            for (int c = 0; c < 4; c++) {
                const float4 D4 = dU4[row4 + c * 32 + lane];
                const float4 A4 = __ldg(a4p + c * 32 + lane);
                const float4 W4 = __ldg(w4p + c * 32 + lane);
                const float4 H4 = __ldg((const float4*)h + ((size_t)b << 7) + c * 32 + lane);
                p0 = fmaf(fmaf(fmaxf(A4.x, 0.f), D4.x, W4.x), H4.x, p0);
                p1 = fmaf(fmaf(fmaxf(A4.y, 0.f), D4.y, W4.y), H4.y, p1);
                p2 = fmaf(fmaf(fmaxf(A4.z, 0.f), D4.z, W4.z), H4.z, p2);
                p3 = fmaf(fmaf(fmaxf(A4.w, 0.f), D4.w, W4.w), H4.w, p3);
            }
#pragma unroll
            for (int c = 0; c < 2; c++) {
                const float4 XW = __ldg(xw4p + c * 32 + lane);
                const float4 X4 = __ldg((const float4*)x + ((size_t)b << 6) + c * 32 + lane);
                p0 = fmaf(XW.x, X4.x, p0);
                p1 = fmaf(XW.y, X4.y, p1);
                p2 = fmaf(XW.z, X4.z, p2);
                p3 = fmaf(XW.w, X4.w, p3);
            }
            float p = (p0 + p1) + (p2 + p3);
#pragma unroll
            for (int off = 16; off; off >>= 1)
                p += __shfl_xor_sync(0xffffffffu, p, off);

            if (lane == 0) {
                const float vb  = v[row];
                const float teS = trace_e[row];
                const float hbi = h[row];
                const float dv  = p + bias;
                const float vn  = fmaf(sv, dv - vb, vb);
                const float nte = fmaf(se, hbi - teS, teS);
                out[OFF_V   + row] = vn;
                out[OFF_NH  + row] = fmaxf(vn, 0.f);
                out[OFF_TEO + row] = nte;
                st_release_gpu(&g_rowflag[row], 1);
            }
        }
        return;
    }

    // ================= p2 consumer =================
    const int pb = bx - 256;          // 0..2047
    const int r0 = pb * 16;           // 16 consecutive rows, same b
    const int b  = r0 >> 9;
    const int j4   = tid & 127;
    const int half = tid >> 7;

    const float sE    = g_sE;
    const float omU   = g_omU;
    const float suMod = g_suMod[b];

    const float4* tE4  = (const float4*)trace_E;
    const float4* up4  = (const float4*)g_up;
    const float4* lo4  = (const float4*)g_lo;
    float4* outDU = (float4*)(out + OFF_DU);
    float4* outTE = (float4*)(out + OFF_TEE);

    // loop-invariant per thread: h and trace_e quarters of batch b
    const float4 hh = __ldg((const float4*)h + ((size_t)b << 7) + j4);
    const float4 te = __ldg((const float4*)trace_e + ((size_t)b << 7) + j4);

    // prefetch step 0 streams
    int    row = r0 + half;
    size_t tsk = ((size_t)row << 7) + j4;
    float4 du  = dU4[tsk];            // L2-hot: producer touched it us ago
    float4 tE  = __ldcs(&tE4[tsk]);

#pragma unroll
    for (int s = 0; s < 8; s++) {
        int rowN = 0; size_t tskN = 0; float4 duN, tEN;
        if (s < 7) {  // prefetch next step BEFORE spinning on this one
            rowN = r0 + 2 * (s + 1) + half;
            tskN = ((size_t)rowN << 7) + j4;
            duN  = dU4[tskN];
            tEN  = __ldcs(&tE4[tskN]);
        }

        if (ld_acquire_gpu(&g_rowflag[row]) == 0) {
            do { __nanosleep(64); } while (ld_acquire_gpu(&g_rowflag[row]) == 0);
        }
        const float nh  = out[OFF_NH  + row];
        const float nte = out[OFF_TEO + row];
        const int   i   = row & 511;
        const float4 up = __ldg(&up4[((size_t)i << 7) + j4]);
        const float4 lo = __ldg(&lo4[((size_t)i << 7) + j4]);

        float4 tOut, dOut;
        {
            const float o = nh * te.x - nte * hh.x;
            tOut.x = fmaf(sE, o - tE.x, tE.x);
            dOut.x = fmaxf(fminf(fmaf(suMod, tOut.x, omU * du.x), up.x), lo.x);
        }
        {
            const float o = nh * te.y - nte * hh.y;
            tOut.y = fmaf(sE, o - tE.y, tE.y);
            dOut.y = fmaxf(fminf(fmaf(suMod, tOut.y, omU * du.y), up.y), lo.y);
        }
        {
            const float o = nh * te.z - nte * hh.z;
            tOut.z = fmaf(sE, o - tE.z, tE.z);
            dOut.z = fmaxf(fminf(fmaf(suMod, tOut.z, omU * du.z), up.z), lo.z);
        }
        {
            const float o = nh * te.w - nte * hh.w;
            tOut.w = fmaf(sE, o - tE.w, tE.w);
            dOut.w = fmaxf(fminf(fmaf(suMod, tOut.w, omU * du.w), up.w), lo.w);
        }
        __stcs(&outTE[tsk], tOut);
        __stcs(&outDU[tsk], dOut);

        row = rowN; tsk = tskN; du = duN; tE = tEN;
    }

    // consume-and-reset flags (this block is the unique reader)
    __syncthreads();
    if (tid < 16) g_rowflag[r0 + tid] = 0;
}

extern "C" void kernel_launch(void* const* d_in, const int* in_sizes, int n_in,
                              void* d_out, int out_size) {
    const float* x       = (const float*)d_in[0];
    const float* h       = (const float*)d_in[1];
    const float* v       = (const float*)d_in[2];
    const float* dU      = (const float*)d_in[3];
    const float* trace_e = (const float*)d_in[4];
    const float* trace_E = (const float*)d_in[5];
    const float* x2h_w   = (const float*)d_in[6];
    const float* x2h_b   = (const float*)d_in[7];
    const float* h2h_w   = (const float*)d_in[8];
    const float* h2h_b   = (const float*)d_in[9];
    const float* alpha   = (const float*)d_in[10];
    const float* tau_v   = (const float*)d_in[11];
    const float* tau_e   = (const float*)d_in[12];
    const float* tau_U   = (const float*)d_in[13];
    const float* tau_E   = (const float*)d_in[14];
    float* out = (float*)d_out;

    prep_kernel<<<320, 256>>>(x, h, x2h_w, x2h_b, h2h_w, h2h_b, alpha,
                              tau_U, tau_E);
    mega_kernel<<<2304, 256>>>(x, h, v, dU, trace_e, trace_E, x2h_w, x2h_b,
                               h2h_w, h2h_b, alpha, tau_v, tau_e, out);
}

// round 15
// speedup vs baseline: 1.2343x; 1.2343x over previous
#include <cuda_runtime.h>
#include <math.h>
#include <stdint.h>

#define Bn 64
#define Dn 256
#define Hn 512
#define Rn 32
#define CLIPV 50.0f

// Output layout (concatenation of the returned tuple, fp32):
//   v_new      [64,512]      @ 0
//   new_h      [64,512]      @ 32768
//   dU_new     [64,512,512]  @ 65536
//   new_trace_e[64,512]      @ 16842752
//   new_trace_E[64,512,512]  @ 16875520
#define OFF_V    ((size_t)0)
#define OFF_NH   ((size_t)32768)
#define OFF_DU   ((size_t)65536)
#define OFF_TEO  ((size_t)16842752)
#define OFF_TEE  ((size_t)16875520)

// Device-global scratch (allocation-free; fully rewritten every launch)
__device__ float g_up[Hn * Hn];
__device__ float g_lo[Hn * Hn];
__device__ float g_suMod[Bn];
__device__ float g_sE;
__device__ float g_omU;
__device__ float g_sv[Hn];
__device__ float g_se[Hn];
__device__ float g_bias[Hn];

__device__ __forceinline__ float sigmoidf_(float x) {
    return 1.0f / (1.0f + expf(-x));
}
__device__ __forceinline__ void cp_async16(uint32_t saddr, const float* gaddr) {
    asm volatile("cp.async.cg.shared.global [%0], [%1], 16;\n"
                 :: "r"(saddr), "l"(gaddr) : "memory");
}
__device__ __forceinline__ void cp_commit() {
    asm volatile("cp.async.commit_group;\n" ::: "memory");
}
__device__ __forceinline__ void cp_wait0() {
    asm volatile("cp.async.wait_group 0;\n" ::: "memory");
}

// ---------------------------------------------------------------------------
// Prep kernel: 320 blocks x 256 threads (~4us).
//   [0,64)   mod blocks: g_suMod[b] (+ scalars at b==0).
//   [64,320) uplo blocks: clip bounds for 2 i-rows; also hoists per-i
//            sigmoids + bias into g_sv/g_se/g_bias (no MUFU in main kernel).
// ---------------------------------------------------------------------------
__global__ __launch_bounds__(256) void prep_kernel(
    const float* __restrict__ x, const float* __restrict__ h,
    const float* __restrict__ x2h_w, const float* __restrict__ x2h_b,
    const float* __restrict__ h2h_w, const float* __restrict__ h2h_b,
    const float* __restrict__ alpha, const float* __restrict__ tau_v,
    const float* __restrict__ tau_e, const float* __restrict__ tau_U,
    const float* __restrict__ tau_E) {
    const int bx   = blockIdx.x;
    const int tid  = threadIdx.x;
    const int warp = tid >> 5;
    const int lane = tid & 31;

    if (bx < 64) {
        const int b = bx;
        __shared__ float sm[8];
        const float4* xb = (const float4*)(x + (size_t)b * Dn);
        const float4* hb = (const float4*)(h + (size_t)b * Hn);

        float acc = 0.f;
#pragma unroll
        for (int t = 0; t < 4; t++) {
            const int o = Hn + warp + 8 * t;
            const float4* xw = (const float4*)(x2h_w + (size_t)o * Dn);
            const float4* hw = (const float4*)(h2h_w + (size_t)o * Hn);
            float s = 0.f;
#pragma unroll
            for (int c = 0; c < 2; c++) {
                const float4 W4 = xw[c * 32 + lane];
                const float4 V4 = xb[c * 32 + lane];
                s = fmaf(W4.x, V4.x, s); s = fmaf(W4.y, V4.y, s);
                s = fmaf(W4.z, V4.z, s); s = fmaf(W4.w, V4.w, s);
            }
#pragma unroll
            for (int c = 0; c < 4; c++) {
                const float4 W4 = hw[c * 32 + lane];
                const float4 V4 = hb[c * 32 + lane];
                s = fmaf(W4.x, V4.x, s); s = fmaf(W4.y, V4.y, s);
                s = fmaf(W4.z, V4.z, s); s = fmaf(W4.w, V4.w, s);
            }
#pragma unroll
            for (int off = 16; off; off >>= 1)
                s += __shfl_xor_sync(0xffffffffu, s, off);
            if (lane == 0) acc += fmaxf(s + x2h_b[o] + h2h_b[o], 0.f);
        }
        if (lane == 0) sm[warp] = acc;
        __syncthreads();
        if (tid == 0) {
            float m = 0.f;
#pragma unroll
            for (int w = 0; w < 8; w++) m += sm[w];
            const float sU = sigmoidf_(tau_U[0]);
            g_suMod[b] = sU * m;
            if (b == 0) {
                g_sE  = sigmoidf_(tau_E[0]);
                g_omU = 1.0f - sU;
            }
        }
        return;
    }

    // uplo blocks: 2 i-rows per block + per-i scalar hoists
    const int i  = (bx - 64) * 2 + (tid >> 7);
    const int j0 = (tid & 127) * 4;
    if ((tid & 127) == 0) {
        g_sv[i]   = sigmoidf_(tau_v[i]);
        g_se[i]   = sigmoidf_(tau_e[i]);
        g_bias[i] = x2h_b[i] + h2h_b[i];
    }
    const float4 W = __ldg((const float4*)(h2h_w + (size_t)i * Hn + j0));
    const float4 A = __ldg((const float4*)(alpha + (size_t)i * Hn + j0));
    float4 up, lo;
    { const float d = fmaxf(A.x, 0.f) + 1e-8f;
      up.x = fmaxf(CLIPV - W.x, 0.f) / d;  lo.x = -fmaxf(CLIPV + W.x, 0.f) / d; }
    { const float d = fmaxf(A.y, 0.f) + 1e-8f;
      up.y = fmaxf(CLIPV - W.y, 0.f) / d;  lo.y = -fmaxf(CLIPV + W.y, 0.f) / d; }
    { const float d = fmaxf(A.z, 0.f) + 1e-8f;
      up.z = fmaxf(CLIPV - W.z, 0.f) / d;  lo.z = -fmaxf(CLIPV + W.z, 0.f) / d; }
    { const float d = fmaxf(A.w, 0.f) + 1e-8f;
      up.w = fmaxf(CLIPV - W.w, 0.f) / d;  lo.w = -fmaxf(CLIPV + W.w, 0.f) / d; }
    *(float4*)(g_up + (size_t)i * Hn + j0) = up;
    *(float4*)(g_lo + (size_t)i * Hn + j0) = lo;
}

// ---------------------------------------------------------------------------
// Main fused kernel: 2048 blocks x 256 threads, 32KB smem, 4 blocks/SM.
// Block owns rows (b, i0..i0+15) — ONE CONTIGUOUS 32KB dU segment.
//  Phase A: cp.async the whole tile to smem (8 independent 16B copies per
//           thread — block-parallel streaming), ONE barrier.
//  Phase B/C: warp w owns rows 2w, 2w+1 from smem: dv reduction
//           (alpha/W/h via __ldg — each matrix <=1MB, L2-resident),
//           butterfly, then IMMEDIATE epilogue with dU from smem.
//           dU touches DRAM exactly once for the entire problem.
//  trace_E streamed with __ldcs; bulk outputs with __stcs.
// ---------------------------------------------------------------------------
__global__ __launch_bounds__(256, 4) void main_kernel(
    const float* __restrict__ x, const float* __restrict__ h,
    const float* __restrict__ v, const float* __restrict__ dU,
    const float* __restrict__ trace_e, const float* __restrict__ trace_E,
    const float* __restrict__ x2h_w, const float* __restrict__ h2h_w,
    const float* __restrict__ alpha, float* __restrict__ out) {
    extern __shared__ float sdu[];   // [16][512]
    const int tid  = threadIdx.x;
    const int warp = tid >> 5;
    const int lane = tid & 31;
    const int b    = blockIdx.x >> 5;
    const int i0   = (blockIdx.x & 31) * 16;

    // ---- Phase A: stream the contiguous 32KB dU tile into smem ----
    const float* duBase = dU + ((size_t)b * Hn + i0) * Hn;  // 8192 floats
    const uint32_t sbase = (uint32_t)__cvta_generic_to_shared(sdu);
#pragma unroll
    for (int k = 0; k < 8; k++) {
        const int idx = tid + k * 256;            // float4 index 0..2047
        cp_async16(sbase + idx * 16, duBase + idx * 4);
    }
    cp_commit();
    cp_wait0();
    __syncthreads();

    const float sE    = g_sE;
    const float omU   = g_omU;
    const float suMod = g_suMod[b];

    const float4* h4p  = (const float4*)h + ((size_t)b << 7);
    const float4* te4p = (const float4*)trace_e + ((size_t)b << 7);
    const float4* x4p  = (const float4*)x + ((size_t)b << 6);
    const float4* up4  = (const float4*)g_up;
    const float4* lo4  = (const float4*)g_lo;
    const float4* tE4  = (const float4*)trace_E;
    float4* outDU = (float4*)(out + OFF_DU);
    float4* outTE = (float4*)(out + OFF_TEE);

#pragma unroll
    for (int half = 0; half < 2; half++) {
        const int r = warp * 2 + half;            // 0..15
        const int i = i0 + r;
        const size_t row  = (size_t)b * Hn + i;
        const size_t row4 = row << 7;
        const float* du = sdu + r * 512;

        const float4* a4p  = (const float4*)alpha + ((size_t)i << 7);
        const float4* w4p  = (const float4*)h2h_w + ((size_t)i << 7);
        const float4* xw4p = (const float4*)x2h_w + ((size_t)i << 6);

        // ---- dv reduction (dU from smem; matrices from L2) ----
        float p0 = 0.f, p1 = 0.f, p2 = 0.f, p3 = 0.f;
#pragma unroll
        for (int c = 0; c < 4; c++) {
            const float4 D4 = *(const float4*)(du + c * 128 + lane * 4);
            const float4 A4 = __ldg(a4p + c * 32 + lane);
            const float4 W4 = __ldg(w4p + c * 32 + lane);
            const float4 H4 = __ldg(h4p + c * 32 + lane);
            p0 = fmaf(fmaf(fmaxf(A4.x, 0.f), D4.x, W4.x), H4.x, p0);
            p1 = fmaf(fmaf(fmaxf(A4.y, 0.f), D4.y, W4.y), H4.y, p1);
            p2 = fmaf(fmaf(fmaxf(A4.z, 0.f), D4.z, W4.z), H4.z, p2);
            p3 = fmaf(fmaf(fmaxf(A4.w, 0.f), D4.w, W4.w), H4.w, p3);
        }
#pragma unroll
        for (int c = 0; c < 2; c++) {
            const float4 XW = __ldg(xw4p + c * 32 + lane);
            const float4 X4 = __ldg(x4p + c * 32 + lane);
            p0 = fmaf(XW.x, X4.x, p0);
            p1 = fmaf(XW.y, X4.y, p1);
            p2 = fmaf(XW.z, X4.z, p2);
            p3 = fmaf(XW.w, X4.w, p3);
        }
        float p = (p0 + p1) + (p2 + p3);
#pragma unroll
        for (int off = 16; off; off >>= 1)
            p += __shfl_xor_sync(0xffffffffu, p, off);

        // per-row scalars (all lanes; broadcast loads)
        const float dv  = p + g_bias[i];
        const float vb  = __ldg(v + row);
        const float vn  = fmaf(g_sv[i], dv - vb, vb);
        const float nh  = fmaxf(vn, 0.f);
        const float teS = __ldg(trace_e + row);
        const float nte = fmaf(g_se[i], __ldg(h + row) - teS, teS);
        if (lane == 0) {
            out[OFF_V   + row] = vn;
            out[OFF_NH  + row] = nh;
            out[OFF_TEO + row] = nte;
        }

        // ---- epilogue: dU from smem, tE streamed ----
#pragma unroll
        for (int c = 0; c < 4; c++) {
            const float4 D4 = *(const float4*)(du + c * 128 + lane * 4);
            const float4 tE = __ldcs(&tE4[row4 + c * 32 + lane]);
            const float4 hh = __ldg(h4p + c * 32 + lane);
            const float4 te = __ldg(te4p + c * 32 + lane);
            const float4 up = __ldg(&up4[((size_t)i << 7) + c * 32 + lane]);
            const float4 lo = __ldg(&lo4[((size_t)i << 7) + c * 32 + lane]);

            float4 tOut, dOut;
            {
                const float o = nh * te.x - nte * hh.x;
                tOut.x = fmaf(sE, o - tE.x, tE.x);
                dOut.x = fmaxf(fminf(fmaf(suMod, tOut.x, omU * D4.x), up.x), lo.x);
            }
            {
                const float o = nh * te.y - nte * hh.y;
                tOut.y = fmaf(sE, o - tE.y, tE.y);
                dOut.y = fmaxf(fminf(fmaf(suMod, tOut.y, omU * D4.y), up.y), lo.y);
            }
            {
                const float o = nh * te.z - nte * hh.z;
                tOut.z = fmaf(sE, o - tE.z, tE.z);
                dOut.z = fmaxf(fminf(fmaf(suMod, tOut.z, omU * D4.z), up.z), lo.z);
            }
            {
                const float o = nh * te.w - nte * hh.w;
                tOut.w = fmaf(sE, o - tE.w, tE.w);
                dOut.w = fmaxf(fminf(fmaf(suMod, tOut.w, omU * D4.w), up.w), lo.w);
            }
            __stcs(&outTE[row4 + c * 32 + lane], tOut);
            __stcs(&outDU[row4 + c * 32 + lane], dOut);
        }
    }
}

extern "C" void kernel_launch(void* const* d_in, const int* in_sizes, int n_in,
                              void* d_out, int out_size) {
    const float* x       = (const float*)d_in[0];
    const float* h       = (const float*)d_in[1];
    const float* v       = (const float*)d_in[2];
    const float* dU      = (const float*)d_in[3];
    const float* trace_e = (const float*)d_in[4];
    const float* trace_E = (const float*)d_in[5];
    const float* x2h_w   = (const float*)d_in[6];
    const float* x2h_b   = (const float*)d_in[7];
    const float* h2h_w   = (const float*)d_in[8];
    const float* h2h_b   = (const float*)d_in[9];
    const float* alpha   = (const float*)d_in[10];
    const float* tau_v   = (const float*)d_in[11];
    const float* tau_e   = (const float*)d_in[12];
    const float* tau_U   = (const float*)d_in[13];
    const float* tau_E   = (const float*)d_in[14];
    float* out = (float*)d_out;

    prep_kernel<<<320, 256>>>(x, h, x2h_w, x2h_b, h2h_w, h2h_b, alpha,
                              tau_v, tau_e, tau_U, tau_E);
    const int smem = 16 * 512 * 4;  // 32KB dU tile
    main_kernel<<<2048, 256, smem>>>(x, h, v, dU, trace_e, trace_E,
                                     x2h_w, h2h_w, alpha, out);
}

// round 16
// speedup vs baseline: 1.3498x; 1.0936x over previous
#include <cuda_runtime.h>
#include <math.h>
#include <stdint.h>

#define Bn 64
#define Dn 256
#define Hn 512
#define Rn 32
#define CLIPV 50.0f
#define TB1 16   // batches per P1 main block

// Output layout (concatenation of the returned tuple, fp32):
//   v_new      [64,512]      @ 0
//   new_h      [64,512]      @ 32768
//   dU_new     [64,512,512]  @ 65536
//   new_trace_e[64,512]      @ 16842752
//   new_trace_E[64,512,512]  @ 16875520
#define OFF_V    ((size_t)0)
#define OFF_NH   ((size_t)32768)
#define OFF_DU   ((size_t)65536)
#define OFF_TEO  ((size_t)16842752)
#define OFF_TEE  ((size_t)16875520)

// Device-global scratch (allocation-free; fully rewritten every launch)
__device__ float g_up[Hn * Hn];
__device__ float g_lo[Hn * Hn];
__device__ float g_suMod[Bn];
__device__ float g_sE;
__device__ float g_omU;

__device__ __forceinline__ float sigmoidf_(float x) {
    return 1.0f / (1.0f + expf(-x));
}
__device__ __forceinline__ void cp_async16(uint32_t saddr, const float* gaddr) {
    asm volatile("cp.async.cg.shared.global [%0], [%1], 16;\n"
                 :: "r"(saddr), "l"(gaddr) : "memory");
}
__device__ __forceinline__ void cp_commit() {
    asm volatile("cp.async.commit_group;\n" ::: "memory");
}
__device__ __forceinline__ void cp_wait3() {
    asm volatile("cp.async.wait_group 3;\n" ::: "memory");
}

// ---------------------------------------------------------------------------
// P1: 576 blocks x 128 threads, 32KB dynamic smem, __launch_bounds__(128,6)
// -> 6 blocks/SM (192KB smem), ONE wave (capacity 912 >= 576).
// Smem = per-warp QUAD-buffered cp.async dU tiles (4 warps x 4 x 2KB = 32KB).
// Per warp: 4 rows in DRAM flight at all times -> 96 rows (192KB) in flight
// per SM (3x the R6 design whose 2-row depth pinned p1 at ~3TB/s).
//  bx < 512 : main slice. gx = bx & 127 -> i-group, gy = bx >> 7 -> b0.
//             Warp-per-i, TB1=16 rows: wait_group 3 pops the oldest tile,
//             consume from smem (conflict-free LDS.128; h/x via __ldg,
//             L1-hot), butterfly, refill row bb+4, commit EVERY iteration
//             (uniform group accounting). Refill is issued after the
//             butterfly that data-depends on the tile -> no WAR hazard.
//             gy==0 blocks also fold in the clip-bound precompute.
//  bx >= 512: mod slice for b = bx - 512 (free, inside the main wave).
// ---------------------------------------------------------------------------
__global__ __launch_bounds__(128, 6) void p1_kernel(
    const float* __restrict__ x, const float* __restrict__ h,
    const float* __restrict__ v, const float* __restrict__ dU,
    const float* __restrict__ trace_e, const float* __restrict__ x2h_w,
    const float* __restrict__ x2h_b, const float* __restrict__ h2h_w,
    const float* __restrict__ h2h_b, const float* __restrict__ alpha,
    const float* __restrict__ tau_v, const float* __restrict__ tau_e,
    const float* __restrict__ tau_U, const float* __restrict__ tau_E,
    float* __restrict__ out) {
    extern __shared__ float smem[];   // 8192 floats: (warp*4 + t)*512
    const int warp = threadIdx.x >> 5;
    const int lane = threadIdx.x & 31;

    if (blockIdx.x >= 512) {
        // ---- mod slice ----
        const int b = blockIdx.x - 512;
        float* sm = smem;  // 4 floats of scratch

        const float4* xb = (const float4*)(x + (size_t)b * Dn);
        const float4* hb = (const float4*)(h + (size_t)b * Hn);

        float acc = 0.f;
#pragma unroll
        for (int t = 0; t < 8; t++) {
            const int o = Hn + warp + 4 * t;
            const float4* xw = (const float4*)(x2h_w + (size_t)o * Dn);
            const float4* hw = (const float4*)(h2h_w + (size_t)o * Hn);
            float s = 0.f;
#pragma unroll
            for (int c = 0; c < 2; c++) {
                const float4 W4 = xw[c * 32 + lane];
                const float4 V4 = xb[c * 32 + lane];
                s = fmaf(W4.x, V4.x, s); s = fmaf(W4.y, V4.y, s);
                s = fmaf(W4.z, V4.z, s); s = fmaf(W4.w, V4.w, s);
            }
#pragma unroll
            for (int c = 0; c < 4; c++) {
                const float4 W4 = hw[c * 32 + lane];
                const float4 V4 = hb[c * 32 + lane];
                s = fmaf(W4.x, V4.x, s); s = fmaf(W4.y, V4.y, s);
                s = fmaf(W4.z, V4.z, s); s = fmaf(W4.w, V4.w, s);
            }
#pragma unroll
            for (int off = 16; off; off >>= 1)
                s += __shfl_xor_sync(0xffffffffu, s, off);
            if (lane == 0) acc += fmaxf(s + x2h_b[o] + h2h_b[o], 0.f);
        }
        if (lane == 0) sm[warp] = acc;
        __syncthreads();
        if (threadIdx.x == 0) {
            const float m  = sm[0] + sm[1] + sm[2] + sm[3];
            const float sU = sigmoidf_(tau_U[0]);
            g_suMod[b] = sU * m;
            if (b == 0) {
                g_sE  = sigmoidf_(tau_E[0]);
                g_omU = 1.0f - sU;
            }
        }
        return;
    }

    // ---- main reduction slice ----
    const int gx = blockIdx.x & 127;
    const int gy = blockIdx.x >> 7;
    const int i  = gx * 4 + warp;
    const int b0 = gy * TB1;
    const int jb = lane * 4;

    // Per-i rows in registers (lane covers 4 chunks of 4 cols)
    float ar[4][4], Wr[4][4];
#pragma unroll
    for (int c = 0; c < 4; c++) {
        const int j = c * 128 + jb;
        const float4 A = __ldg((const float4*)(alpha + (size_t)i * Hn + j));
        const float4 W = __ldg((const float4*)(h2h_w + (size_t)i * Hn + j));
        ar[c][0] = fmaxf(A.x, 0.f); ar[c][1] = fmaxf(A.y, 0.f);
        ar[c][2] = fmaxf(A.z, 0.f); ar[c][3] = fmaxf(A.w, 0.f);
        Wr[c][0] = W.x; Wr[c][1] = W.y; Wr[c][2] = W.z; Wr[c][3] = W.w;
    }

    // Clip-bound fold: one block column computes up/lo.
    if (gy == 0) {
#pragma unroll
        for (int c = 0; c < 4; c++) {
            const int j = c * 128 + jb;
            float4 up, lo;
            float* u = (float*)&up;
            float* l = (float*)&lo;
#pragma unroll
            for (int k = 0; k < 4; k++) {
                const float d = ar[c][k] + 1e-8f;
                u[k] =  fmaxf(CLIPV - Wr[c][k], 0.f) / d;
                l[k] = -fmaxf(CLIPV + Wr[c][k], 0.f) / d;
            }
            *(float4*)(g_up + (size_t)i * Hn + j) = up;
            *(float4*)(g_lo + (size_t)i * Hn + j) = lo;
        }
    }

    float xw[2][4];
#pragma unroll
    for (int c = 0; c < 2; c++) {
        const float4 X = __ldg((const float4*)(x2h_w + (size_t)i * Dn + c * 128 + jb));
        xw[c][0] = X.x; xw[c][1] = X.y; xw[c][2] = X.z; xw[c][3] = X.w;
    }
    const float bias = x2h_b[i] + h2h_b[i];
    const float sv   = sigmoidf_(tau_v[i]);
    const float se   = sigmoidf_(tau_e[i]);

    // Quad-buffered per-warp tiles. Single float-index helper, scaled once
    // to bytes for cp.async (R9's unit-mismatch bug class eliminated).
    const uint32_t sbase = (uint32_t)__cvta_generic_to_shared(smem);
    const float* dUrow = dU + ((size_t)b0 * Hn + i) * Hn;  // row base for b0
    const size_t bstride = (size_t)Hn * Hn;                // next b, same i

    // prime the pipeline: rows 0..3 into tiles 0..3 (4 groups outstanding)
#pragma unroll
    for (int t = 0; t < 4; t++) {
        const int tbase = (warp * 4 + t) * 512;
        const float* g = dUrow + (size_t)t * bstride;
#pragma unroll
        for (int c = 0; c < 4; c++)
            cp_async16(sbase + (uint32_t)(tbase + c * 128 + jb) * 4,
                       g + c * 128 + jb);
        cp_commit();
    }

    for (int bb = 0; bb < TB1; bb++) {
        const int b = b0 + bb;
        // tile bb was loaded by commit #(bb+1); wait_group 3 guarantees
        // all but the newest 3 groups are complete -> tile bb ready.
        cp_wait3();

        const int tbase = (warp * 4 + (bb & 3)) * 512;
        const float* buf = smem + tbase + jb;

        float p0 = 0.f, p1 = 0.f, p2 = 0.f, p3 = 0.f;
#pragma unroll
        for (int c = 0; c < 4; c++) {
            const float4 D4 = *(const float4*)(buf + c * 128);
            const float4 H4 = __ldg((const float4*)h + ((size_t)b << 7) + c * 32 + lane);
            p0 = fmaf(fmaf(ar[c][0], D4.x, Wr[c][0]), H4.x, p0);
            p1 = fmaf(fmaf(ar[c][1], D4.y, Wr[c][1]), H4.y, p1);
            p2 = fmaf(fmaf(ar[c][2], D4.z, Wr[c][2]), H4.z, p2);
            p3 = fmaf(fmaf(ar[c][3], D4.w, Wr[c][3]), H4.w, p3);
        }
#pragma unroll
        for (int c = 0; c < 2; c++) {
            const float4 X4 = __ldg((const float4*)x + ((size_t)b << 6) + c * 32 + lane);
            p0 = fmaf(xw[c][0], X4.x, p0);
            p1 = fmaf(xw[c][1], X4.y, p1);
            p2 = fmaf(xw[c][2], X4.z, p2);
            p3 = fmaf(xw[c][3], X4.w, p3);
        }
        float p = (p0 + p1) + (p2 + p3);
#pragma unroll
        for (int off = 16; off; off >>= 1)
            p += __shfl_xor_sync(0xffffffffu, p, off);
        // butterfly done -> LDS reads of this tile completed; refill safe.

        if (bb + 4 < TB1) {
            const float* g = dUrow + (size_t)(bb + 4) * bstride;
#pragma unroll
            for (int c = 0; c < 4; c++)
                cp_async16(sbase + (uint32_t)(tbase + c * 128 + jb) * 4,
                           g + c * 128 + jb);
        }
        cp_commit();  // always commit: uniform group accounting

        if (lane == 0) {
            const size_t row = (size_t)b * Hn + i;
            const float vb  = __ldg(v + row);
            const float teS = __ldg(trace_e + row);
            const float hbi = __ldg(h + row);
            const float dv  = p + bias;
            const float vn  = fmaf(sv, dv - vb, vb);
            const float nte = fmaf(se, hbi - teS, teS);
            out[OFF_V   + row] = vn;
            out[OFF_NH  + row] = fmaxf(vn, 0.f);
            out[OFF_TEO + row] = nte;
        }
    }
}

// ---------------------------------------------------------------------------
// P2: pure streaming elementwise pass over the HxH matrices.
// 4 independent tasks per thread; trace_E via __ldcs; outputs via __stcs.
// dU is L2-warm from p1.
// ---------------------------------------------------------------------------
#define P2_BLOCKS 4096
#define P2_THREADS 256
#define P2_TOTAL  ((size_t)Bn * Hn * 128)
#define P2_QTR    (P2_TOTAL / 4)

__global__ __launch_bounds__(P2_THREADS) void p2_kernel(
    const float* __restrict__ dU, const float* __restrict__ trace_E,
    const float* __restrict__ h, const float* __restrict__ trace_e,
    float* __restrict__ out) {
    const size_t gid = (size_t)blockIdx.x * P2_THREADS + threadIdx.x;
    const float sE  = g_sE;
    const float omU = g_omU;

    const float4* dU4 = (const float4*)dU;
    const float4* tE4 = (const float4*)trace_E;
    const float4* h4p = (const float4*)h;
    const float4* te4p = (const float4*)trace_e;
    const float4* up4 = (const float4*)g_up;
    const float4* lo4 = (const float4*)g_lo;
    float4* outDU = (float4*)(out + OFF_DU);
    float4* outTE = (float4*)(out + OFF_TEE);

#pragma unroll
    for (int q = 0; q < 4; q++) {
        const size_t t = gid + (size_t)q * P2_QTR;
        const int j4  = (int)(t & 127);
        const size_t row = t >> 7;           // b*512 + i
        const int i = (int)(row & 511);
        const int b = (int)(row >> 9);

        const float4 du = dU4[t];
        const float4 tE = __ldcs(&tE4[t]);
        const float4 hh = h4p[((size_t)b << 7) + j4];
        const float4 te = te4p[((size_t)b << 7) + j4];
        const float4 up = up4[((size_t)i << 7) + j4];
        const float4 lo = lo4[((size_t)i << 7) + j4];
        const float nh  = __ldg(out + OFF_NH  + row);
        const float nte = __ldg(out + OFF_TEO + row);
        const float suMod = g_suMod[b];

        float4 tOut, dOut;
        {
            const float o = nh * te.x - nte * hh.x;
            tOut.x = fmaf(sE, o - tE.x, tE.x);
            dOut.x = fmaxf(fminf(fmaf(suMod, tOut.x, omU * du.x), up.x), lo.x);
        }
        {
            const float o = nh * te.y - nte * hh.y;
            tOut.y = fmaf(sE, o - tE.y, tE.y);
            dOut.y = fmaxf(fminf(fmaf(suMod, tOut.y, omU * du.y), up.y), lo.y);
        }
        {
            const float o = nh * te.z - nte * hh.z;
            tOut.z = fmaf(sE, o - tE.z, tE.z);
            dOut.z = fmaxf(fminf(fmaf(suMod, tOut.z, omU * du.z), up.z), lo.z);
        }
        {
            const float o = nh * te.w - nte * hh.w;
            tOut.w = fmaf(sE, o - tE.w, tE.w);
            dOut.w = fmaxf(fminf(fmaf(suMod, tOut.w, omU * du.w), up.w), lo.w);
        }
        __stcs(&outTE[t], tOut);
        __stcs(&outDU[t], dOut);
    }
}

extern "C" void kernel_launch(void* const* d_in, const int* in_sizes, int n_in,
                              void* d_out, int out_size) {
    const float* x       = (const float*)d_in[0];
    const float* h       = (const float*)d_in[1];
    const float* v       = (const float*)d_in[2];
    const float* dU      = (const float*)d_in[3];
    const float* trace_e = (const float*)d_in[4];
    const float* trace_E = (const float*)d_in[5];
    const float* x2h_w   = (const float*)d_in[6];
    const float* x2h_b   = (const float*)d_in[7];
    const float* h2h_w   = (const float*)d_in[8];
    const float* h2h_b   = (const float*)d_in[9];
    const float* alpha   = (const float*)d_in[10];
    const float* tau_v   = (const float*)d_in[11];
    const float* tau_e   = (const float*)d_in[12];
    const float* tau_U   = (const float*)d_in[13];
    const float* tau_E   = (const float*)d_in[14];
    float* out = (float*)d_out;

    const int p1_smem = 8192 * 4;  // 32KB: per-warp quad-buffered dU tiles
    p1_kernel<<<576, 128, p1_smem>>>(x, h, v, dU, trace_e, x2h_w, x2h_b,
                                     h2h_w, h2h_b, alpha, tau_v, tau_e,
                                     tau_U, tau_E, out);
    p2_kernel<<<P2_BLOCKS, P2_THREADS>>>(dU, trace_E, h, trace_e, out);
}